// round 1
// baseline (speedup 1.0000x reference)
#include <cuda_runtime.h>
#include <math.h>

// Problem constants (fixed by the reference)
#define BB 16
#define QQ 300
#define CC 256
#define NHH 8
#define DHH 32
#define SUMP 16
#define SS 8500           // 80*80+40*40+20*20+10*10
#define BQ (BB*QQ)        // 4800

// scratch: sampling locations (B*Q, NH*SUMP*2) = 4800*256 floats
__device__ float g_loc[BQ * 256];

__device__ __constant__ int cW[4]     = {80, 40, 20, 10};
__device__ __constant__ int cStart[4] = {0, 6400, 8000, 8400};

// ---------------------------------------------------------------------------
// Kernel 1: offsets + attention logits GEMM, softmax, sampling-loc computation
// Block = 384 threads, handles 16 (b,q) rows.
//   threads [0,256):   offset columns (h,p,axis)
//   threads [256,384): attn columns (h,p)
// ---------------------------------------------------------------------------
__global__ __launch_bounds__(384) void dfine_k1(
    const float* __restrict__ hs,      // (B,Q,C)
    const float* __restrict__ refp,    // (B,Q,1,4)
    const float* __restrict__ offk,    // (C, NH, SUMP, 2) -> c*256 + col
    const float* __restrict__ offb,    // (NH, SUMP, 2)
    const float* __restrict__ attnk,   // (C, NH, SUMP)    -> c*128 + col
    const float* __restrict__ attnb,   // (NH, SUMP)
    const float* __restrict__ nps,     // (SUMP,)
    float* __restrict__ attn_out)      // (B,Q,NH,SUMP) region of d_out
{
    __shared__ float sA[16][CC];
    __shared__ float sL[16][128];

    const int t   = threadIdx.x;        // 0..383
    const int bq0 = blockIdx.x * 16;

    // load 16 rows of hidden_states into smem
    for (int i = t; i < 16 * CC; i += 384) {
        sA[i >> 8][i & 255] = hs[(size_t)bq0 * CC + i];
    }
    __syncthreads();

    float acc[16];
#pragma unroll
    for (int r = 0; r < 16; r++) acc[r] = 0.f;

    if (t < 256) {
        const float* col = offk + t;          // stride 256 per c
#pragma unroll 4
        for (int c = 0; c < CC; c++) {
            float bv = __ldg(col + (size_t)c * 256);
#pragma unroll
            for (int r = 0; r < 16; r++) acc[r] = fmaf(sA[r][c], bv, acc[r]);
        }
    } else {
        const int cl = t - 256;               // 0..127
        const float* col = attnk + cl;        // stride 128 per c
#pragma unroll 4
        for (int c = 0; c < CC; c++) {
            float bv = __ldg(col + (size_t)c * 128);
#pragma unroll
            for (int r = 0; r < 16; r++) acc[r] = fmaf(sA[r][c], bv, acc[r]);
        }
    }

    // attention path: bias -> smem logits
    if (t >= 256) {
        const int cl = t - 256;
        const float bias = attnb[cl];
#pragma unroll
        for (int r = 0; r < 16; r++) sL[r][cl] = acc[r] + bias;
    }
    __syncthreads();

    if (t >= 256) {
        // softmax over the 16 points of this head, per row
        const int cl   = t - 256;
        const int base = (cl >> 4) << 4;      // start of this head's group
#pragma unroll
        for (int r = 0; r < 16; r++) {
            float m = -1e30f;
#pragma unroll
            for (int p = 0; p < 16; p++) m = fmaxf(m, sL[r][base + p]);
            float s = 0.f;
#pragma unroll
            for (int p = 0; p < 16; p++) s += __expf(sL[r][base + p] - m);
            float w = __expf(sL[r][cl] - m) / s;
            attn_out[(size_t)(bq0 + r) * 128 + cl] = w;
        }
    } else {
        // offset path: bias, scale by num_points_scale * wh * 0.5, add center
        const int axis = t & 1;
        const int p    = (t >> 1) & 15;
        const float bias  = offb[t];
        const float scale = nps[p] * 0.5f;
#pragma unroll
        for (int r = 0; r < 16; r++) {
            const float* rp = refp + (size_t)(bq0 + r) * 4;
            float center = rp[axis];
            float wh     = rp[2 + axis];
            float off    = acc[r] + bias;
            g_loc[(size_t)(bq0 + r) * 256 + t] = fmaf(off * scale, wh, center);
        }
    }
}

// ---------------------------------------------------------------------------
// Kernel 2: bilinear sampling + attention-weighted accumulation
// One warp per (b,q,h); lane = d (head dim). 8 warps/block.
// ---------------------------------------------------------------------------
__global__ __launch_bounds__(256) void dfine_k2(
    const float* __restrict__ enc,     // (B, S, C)
    const float* __restrict__ attn,    // (B,Q,NH,SUMP)
    float* __restrict__ out)           // (B,Q,C)
{
    const int gw   = blockIdx.x * 8 + (threadIdx.x >> 5);
    const int lane = threadIdx.x & 31;
    const int bq   = gw >> 3;
    const int h    = gw & 7;
    const int b    = bq / QQ;

    const float* vbase = enc + (size_t)b * SS * CC + h * DHH + lane;
    const float* lptr  = g_loc + (size_t)bq * 256 + h * 32;
    const float* aptr  = attn + (size_t)bq * 128 + h * 16;

    float acc = 0.f;
#pragma unroll
    for (int p = 0; p < SUMP; p++) {
        const int lvl   = p >> 2;
        const int Wl    = cW[lvl];       // H == W at every level
        const int start = cStart[lvl];

        const float lx = lptr[p * 2];
        const float ly = lptr[p * 2 + 1];
        const float aw = aptr[p];

        float x = lx * (float)Wl - 0.5f;
        float y = ly * (float)Wl - 0.5f;
        float x0f = floorf(x), y0f = floorf(y);
        float fx = x - x0f, fy = y - y0f;
        int x0 = (int)x0f, y0 = (int)y0f;
        int x1 = x0 + 1,   y1 = y0 + 1;

        float w00 = (1.f - fx) * (1.f - fy);
        float w10 = fx * (1.f - fy);
        float w01 = (1.f - fx) * fy;
        float w11 = fx * fy;

        bool xv0 = (x0 >= 0) & (x0 < Wl);
        bool xv1 = (x1 >= 0) & (x1 < Wl);
        bool yv0 = (y0 >= 0) & (y0 < Wl);
        bool yv1 = (y1 >= 0) & (y1 < Wl);

        float sval = 0.f;
        if (xv0 & yv0) sval = fmaf(w00, __ldg(vbase + (size_t)(start + y0 * Wl + x0) * CC), sval);
        if (xv1 & yv0) sval = fmaf(w10, __ldg(vbase + (size_t)(start + y0 * Wl + x1) * CC), sval);
        if (xv0 & yv1) sval = fmaf(w01, __ldg(vbase + (size_t)(start + y1 * Wl + x0) * CC), sval);
        if (xv1 & yv1) sval = fmaf(w11, __ldg(vbase + (size_t)(start + y1 * Wl + x1) * CC), sval);

        acc = fmaf(aw, sval, acc);
    }

    out[(size_t)bq * CC + h * DHH + lane] = acc;
}

// ---------------------------------------------------------------------------
// Launch
// Inputs (metadata order = setup_inputs dict order):
//  0 hidden_states (B,Q,C)            f32
//  1 encoder_hidden_states (B,S,C)    f32
//  2 reference_points (B,Q,1,4)       f32
//  3 off_kernel (C,NH,SUMP,2)         f32
//  4 off_bias (NH,SUMP,2)             f32
//  5 attn_kernel (C,NH,SUMP)          f32
//  6 attn_bias (NH,SUMP)              f32
//  7 num_points_scale (SUMP,)         f32
//  8 spatial_shapes (4,2)             i32 (unused; compile-time constants)
// Output: out (B,Q,C) flat followed by attn (B,Q,NH,SUMP) flat.
// ---------------------------------------------------------------------------
extern "C" void kernel_launch(void* const* d_in, const int* in_sizes, int n_in,
                              void* d_out, int out_size) {
    const float* hs    = (const float*)d_in[0];
    const float* enc   = (const float*)d_in[1];
    const float* refp  = (const float*)d_in[2];
    const float* offk  = (const float*)d_in[3];
    const float* offb  = (const float*)d_in[4];
    const float* attnk = (const float*)d_in[5];
    const float* attnb = (const float*)d_in[6];
    const float* nps   = (const float*)d_in[7];

    float* out      = (float*)d_out;
    float* attn_out = out + (size_t)BQ * CC;   // attn region after main output

    dfine_k1<<<BQ / 16, 384>>>(hs, refp, offk, offb, attnk, attnb, nps, attn_out);
    dfine_k2<<<BQ, 256>>>(enc, attn_out, out);
}